// round 4
// baseline (speedup 1.0000x reference)
#include <cuda_runtime.h>
#include <math.h>

// Problem constants (fixed by the reference)
#define BB   4
#define TT   4
#define CC   32
#define NN   16384
#define FF   64
#define KK   9
#define PADD 4

// Tiling
#define NT       256            // n positions per block
#define WD       128            // duplicated-weight row: 64 f values, each stored twice
#define XSTRIDE  (NT + 2*PADD)  // 264

// SMEM layout sizes (floats)
#define SW_ELEMS   (CC * KK * WD)        // 36864  (144 KB)
#define SX_ELEMS   (CC * XSTRIDE)        // 8448   (33 KB)
#define SC_ELEMS   (3 * XSTRIDE)         // 792
#define SDW_ELEMS  (KK * NT)             // 2304
#define SMEM_FLOATS (SW_ELEMS + SX_ELEMS + SC_ELEMS + SDW_ELEMS)

typedef unsigned long long u64;

// Packed fp32x2 ops (sm_100+; SASS FFMA2/FMUL2 — ptxas never auto-emits these)
#define FMA2(d, a, b, c) asm("fma.rn.f32x2 %0, %1, %2, %3;" : "=l"(d) : "l"(a), "l"(b), "l"(c))
#define MUL2(d, a, b)    asm("mul.rn.f32x2 %0, %1, %2;"     : "=l"(d) : "l"(a), "l"(b))
#define PACK2(d, lo, hi) asm("mov.b64 %0, {%1, %2};"        : "=l"(d) : "f"(lo), "f"(hi))

__device__ __forceinline__ float decode_sigma(const void* p) {
    const unsigned* w = (const unsigned*)p;
    unsigned lo = w[0];
    if (lo >= 1u && lo <= 1000000u) return (float)lo;          // int32 / int64 low word
    float f = __uint_as_float(lo);
    if (f > 1e-6f && f < 1e6f) return f;                        // float32
    return (float)(*(const double*)p);                          // float64
}

__global__ __launch_bounds__(256, 1)
void swconv1d_kernel(const float* __restrict__ x,
                     const float* __restrict__ coords,
                     const float* __restrict__ weight,
                     const void*  __restrict__ sig,
                     float* __restrict__ out)
{
    extern __shared__ float sm[];
    float* s_w  = sm;                          // [C*K][WD]  duplicated: s_w[ck*128 + 2f] = s_w[..+2f+1] = w[f]
    float* s_x  = s_w + SW_ELEMS;              // [C][XSTRIDE]
    float* s_c  = s_x + SX_ELEMS;              // [3][XSTRIDE]
    float* s_dw = s_c + SC_ELEMS;              // [K][NT]

    const int tid    = threadIdx.x;
    const int bt     = blockIdx.y;             // 0..15
    const int t      = bt & 3;
    const int n_base = blockIdx.x * NT;

    const float inv_sigma = 1.0f / decode_sigma(sig);

    // ---- stage weight[t], transposed + duplicated: row ck, pair slot f ----
    {
        const float* wt = weight + (size_t)t * FF * CC * KK;
        for (int i = tid; i < FF * CC * KK; i += 256) {
            int f  = i / (CC * KK);
            int ck = i - f * (CC * KK);
            float v = wt[i];
            *(float2*)&s_w[ck * WD + 2 * f] = make_float2(v, v);
        }
    }

    // ---- stage x tile (zero-padded) ----
    {
        const float* xb = x + (size_t)bt * CC * NN;
        for (int i = tid; i < SX_ELEMS; i += 256) {
            int c = i / XSTRIDE;
            int m = i - c * XSTRIDE;
            int n = n_base + m - PADD;
            s_x[i] = (n >= 0 && n < NN) ? xb[c * NN + n] : 0.0f;
        }
    }

    // ---- stage coords tile (zero-padded) ----
    {
        const float* cb = coords + (size_t)bt * 3 * NN;
        for (int i = tid; i < SC_ELEMS; i += 256) {
            int c = i / XSTRIDE;
            int m = i - c * XSTRIDE;
            int n = n_base + m - PADD;
            s_c[i] = (n >= 0 && n < NN) ? cb[c * NN + n] : 0.0f;
        }
    }
    __syncthreads();

    // ---- distance weights dw[k][j] = max(0, 1 - |coords(n+k-4) - coords(n)| / sigma) ----
    for (int i = tid; i < KK * NT; i += 256) {
        int k = i / NT;
        int j = i - k * NT;
        float d0 = s_c[0 * XSTRIDE + j + k] - s_c[0 * XSTRIDE + j + PADD];
        float d1 = s_c[1 * XSTRIDE + j + k] - s_c[1 * XSTRIDE + j + PADD];
        float d2 = s_c[2 * XSTRIDE + j + k] - s_c[2 * XSTRIDE + j + PADD];
        float dd = d0 * d0 + d1 * d1 + d2 * d2;
        float w  = 1.0f - sqrtf(dd) * inv_sigma;
        s_dw[i]  = w > 0.0f ? w : 0.0f;
    }
    __syncthreads();

    // ---- register-tiled compute: 8 f x 8 n per thread, fp32x2 packed over n ----
    const int tx    = tid & 31;     // n group (whole warp shares ty -> weight loads broadcast)
    const int ty    = tid >> 5;     // f group
    const int n0    = tx * 8;       // local n offset within tile

    // dw pairs for this thread's 8 n positions, all 9 taps (aligned 64-bit loads)
    u64 dwr2[KK][4];
    #pragma unroll
    for (int k = 0; k < KK; ++k) {
        ulonglong2 a = *(const ulonglong2*)&s_dw[k * NT + n0];
        ulonglong2 b = *(const ulonglong2*)&s_dw[k * NT + n0 + 4];
        dwr2[k][0] = a.x; dwr2[k][1] = a.y; dwr2[k][2] = b.x; dwr2[k][3] = b.y;
    }

    u64 acc2[8][4];
    #pragma unroll
    for (int f = 0; f < 8; ++f)
        #pragma unroll
        for (int j = 0; j < 4; ++j) acc2[f][j] = 0ULL;

    const float* swt = s_w + ty * 16;   // this warp's duplicated f-slice (broadcast within warp)

    for (int c = 0; c < CC; ++c) {
        // 16-wide x window covers all 9 taps
        float xr[16];
        #pragma unroll
        for (int q = 0; q < 4; ++q) {
            float4 v = *(const float4*)&s_x[c * XSTRIDE + n0 + q * 4];
            xr[q * 4 + 0] = v.x; xr[q * 4 + 1] = v.y;
            xr[q * 4 + 2] = v.z; xr[q * 4 + 3] = v.w;
        }
        // even- and odd-offset pairs (packed once per c, amortized over 9 taps)
        u64 xe[8], xo[7];
        #pragma unroll
        for (int p = 0; p < 8; ++p) PACK2(xe[p], xr[2 * p], xr[2 * p + 1]);
        #pragma unroll
        for (int p = 0; p < 7; ++p) PACK2(xo[p], xr[2 * p + 1], xr[2 * p + 2]);

        #pragma unroll
        for (int k = 0; k < KK; ++k) {
            // weights: 8 duplicated pairs = 64B, broadcast across the warp
            const ulonglong2* wp = (const ulonglong2*)(swt + (c * KK + k) * WD);
            ulonglong2 w01 = wp[0], w23 = wp[1], w45 = wp[2], w67 = wp[3];
            u64 wv2[8] = {w01.x, w01.y, w23.x, w23.y, w45.x, w45.y, w67.x, w67.y};

            u64 ux2[4];
            #pragma unroll
            for (int j = 0; j < 4; ++j) {
                u64 xp = (k & 1) ? xo[(k - 1) / 2 + j] : xe[k / 2 + j];
                MUL2(ux2[j], xp, dwr2[k][j]);
            }

            #pragma unroll
            for (int f = 0; f < 8; ++f)
                #pragma unroll
                for (int j = 0; j < 4; ++j)
                    FMA2(acc2[f][j], wv2[f], ux2[j], acc2[f][j]);
        }
    }

    // ---- write out[b][t][f][n] (pairs are exactly consecutive n) ----
    float* ob = out + (size_t)bt * FF * NN;
    #pragma unroll
    for (int f = 0; f < 8; ++f) {
        float* orow = ob + (size_t)(ty * 8 + f) * NN + n_base + n0;
        ulonglong2 v0, v1;
        v0.x = acc2[f][0]; v0.y = acc2[f][1];
        v1.x = acc2[f][2]; v1.y = acc2[f][3];
        *(ulonglong2*)&orow[0] = v0;
        *(ulonglong2*)&orow[4] = v1;
    }
}

extern "C" void kernel_launch(void* const* d_in, const int* in_sizes, int n_in,
                              void* d_out, int out_size)
{
    const float* x      = (const float*)d_in[0];
    const float* coords = (const float*)d_in[1];
    const float* weight = (const float*)d_in[2];
    const void*  sig    = d_in[3];
    float*       out    = (float*)d_out;

    size_t smem_bytes = (size_t)SMEM_FLOATS * sizeof(float);   // ~189 KB
    cudaFuncSetAttribute(swconv1d_kernel,
                         cudaFuncAttributeMaxDynamicSharedMemorySize,
                         (int)smem_bytes);

    dim3 grid(NN / NT, BB * TT);   // (64, 16)
    swconv1d_kernel<<<grid, 256, smem_bytes>>>(x, coords, weight, sig, out);
}

// round 8
// speedup vs baseline: 2.3965x; 2.3965x over previous
#include <cuda_runtime.h>
#include <cstdint>
#include <math.h>

// Problem constants
#define BB   4
#define TT   4
#define CC   32
#define NN   16384
#define FF   64
#define KK   9
#define PADD 4

// Tiling
#define NT    256               // n per block
#define XS    (NT + 2*PADD)     // 264
#define KDIM  (CC * KK)         // 288 = GEMM K
#define WST   72                // padded f-stride of B tile (bank-conflict-free)

// SMEM layout (floats)
#define SWB_ELEMS  (KDIM * WST)      // 20736 (82.9 KB) : tf32 W, s_wb[q*72 + f]
#define SX_ELEMS   (CC * XS)         // 8448
#define SC_ELEMS   (3 * XS)          // 792
#define SDW_ELEMS  (KK * NT)         // 2304
#define SMEM_FLOATS (SWB_ELEMS + SX_ELEMS + SC_ELEMS + SDW_ELEMS)   // ~126 KB

__device__ __forceinline__ unsigned f2tf32(float f) {
    unsigned r;
    asm("cvt.rn.tf32.f32 %0, %1;" : "=r"(r) : "f"(f));
    return r;
}

#define MMA_TF32(d, a0, a1, a2, a3, b0, b1)                                   \
    asm volatile("mma.sync.aligned.m16n8k8.row.col.f32.tf32.tf32.f32 "        \
                 "{%0,%1,%2,%3}, {%4,%5,%6,%7}, {%8,%9}, {%0,%1,%2,%3};"      \
                 : "+f"(d[0]), "+f"(d[1]), "+f"(d[2]), "+f"(d[3])             \
                 : "r"(a0), "r"(a1), "r"(a2), "r"(a3), "r"(b0), "r"(b1))

__device__ __forceinline__ float decode_sigma(const void* p) {
    const unsigned* w = (const unsigned*)p;
    unsigned lo = w[0];
    if (lo >= 1u && lo <= 1000000u) return (float)lo;          // int32/int64 low word
    float f = __uint_as_float(lo);
    if (f > 1e-6f && f < 1e6f) return f;                        // float32
    return (float)(*(const double*)p);                          // float64
}

__global__ __launch_bounds__(256)
void swconv1d_mma_kernel(const float* __restrict__ x,
                         const float* __restrict__ coords,
                         const float* __restrict__ weight,
                         const void*  __restrict__ sig,
                         float* __restrict__ out)
{
    extern __shared__ float sm[];
    unsigned* s_wb = (unsigned*)sm;            // [KDIM][WST] tf32: s_wb[q*72 + f]
    float*    s_x  = sm + SWB_ELEMS;           // [C][XS]
    float*    s_c  = s_x + SX_ELEMS;           // [3][XS]
    float*    s_dw = s_c + SC_ELEMS;           // [K][NT]

    const int tid    = threadIdx.x;
    const int wid    = tid >> 5;
    const int lane   = tid & 31;
    const int gid    = lane >> 2;              // groupID (0..7)
    const int tig    = lane & 3;               // threadID_in_group (0..3)
    const int bt     = blockIdx.y;
    const int t      = bt & 3;
    const int n_base = blockIdx.x * NT;

    const float inv_sigma = 1.0f / decode_sigma(sig);

    // ---- stage W[t] as tf32: s_wb[q*72 + f], q = k*32 + c ----
    {
        const float* wt = weight + (size_t)t * FF * KDIM;
        for (int i = tid; i < FF * KDIM; i += 256) {
            int f  = i / KDIM;
            int ck = i - f * KDIM;             // = c*9 + k
            int c  = ck / KK;
            int k  = ck - c * KK;
            s_wb[(k * 32 + c) * WST + f] = f2tf32(wt[i]);
        }
    }
    // ---- stage x tile (zero-padded) ----
    {
        const float* xb = x + (size_t)bt * CC * NN;
        for (int i = tid; i < SX_ELEMS; i += 256) {
            int c = i / XS;
            int m = i - c * XS;
            int n = n_base + m - PADD;
            s_x[i] = (n >= 0 && n < NN) ? xb[c * NN + n] : 0.0f;
        }
    }
    // ---- stage coords tile (zero-padded) ----
    {
        const float* cb = coords + (size_t)bt * 3 * NN;
        for (int i = tid; i < SC_ELEMS; i += 256) {
            int c = i / XS;
            int m = i - c * XS;
            int n = n_base + m - PADD;
            s_c[i] = (n >= 0 && n < NN) ? cb[c * NN + n] : 0.0f;
        }
    }
    __syncthreads();

    // ---- distance weights dw[k][j] = max(0, 1 - |dcoords| / sigma) ----
    for (int i = tid; i < KK * NT; i += 256) {
        int k = i / NT;
        int j = i - k * NT;
        float d0 = s_c[0 * XS + j + k] - s_c[0 * XS + j + PADD];
        float d1 = s_c[1 * XS + j + k] - s_c[1 * XS + j + PADD];
        float d2 = s_c[2 * XS + j + k] - s_c[2 * XS + j + PADD];
        float dd = d0 * d0 + d1 * d1 + d2 * d2;
        float w  = 1.0f - sqrtf(dd) * inv_sigma;
        s_dw[i]  = w > 0.0f ? w : 0.0f;
    }
    __syncthreads();

    // ---- warp GEMM: each warp owns 32 n (2 m16 tiles) x 64 f (8 n8 tiles) ----
    // D = U[n,288] x W^T[288,64]; A frags built on the fly: U[n][k*32+c] = x[c][n+k-4]*dw[k][n]
    const int n0 = wid * 32 + gid;   // this thread's base n-row (A/D row = groupID)

    float acc[2][8][4];
    #pragma unroll
    for (int mt = 0; mt < 2; ++mt)
        #pragma unroll
        for (int ft = 0; ft < 8; ++ft)
            #pragma unroll
            for (int r = 0; r < 4; ++r) acc[mt][ft][r] = 0.0f;

    #pragma unroll 1
    for (int k = 0; k < KK; ++k) {
        // dw for this tap at this thread's 4 row positions
        const float dw00 = s_dw[k * NT + n0];
        const float dw01 = s_dw[k * NT + n0 + 8];
        const float dw10 = s_dw[k * NT + n0 + 16];
        const float dw11 = s_dw[k * NT + n0 + 24];
        const float* xk = s_x + n0 + k;        // x[c][n0 + k - 4 + 4] base

        #pragma unroll
        for (int ks = 0; ks < 4; ++ks) {       // K-step s = k*4 + ks (8 c's each)
            const int cb = ks * 8 + tig;       // A col (K) = tig, tig+4 within chunk
            const float* xc0 = xk + cb * XS;
            const float* xc4 = xk + (cb + 4) * XS;

            // A fragments (rows gid / gid+8 of each m16 tile)
            unsigned a00 = f2tf32(xc0[0]  * dw00);
            unsigned a01 = f2tf32(xc0[8]  * dw01);
            unsigned a02 = f2tf32(xc4[0]  * dw00);
            unsigned a03 = f2tf32(xc4[8]  * dw01);
            unsigned a10 = f2tf32(xc0[16] * dw10);
            unsigned a11 = f2tf32(xc0[24] * dw11);
            unsigned a12 = f2tf32(xc4[16] * dw10);
            unsigned a13 = f2tf32(xc4[24] * dw11);

            // B fragments: b0 = W^T[qb+tig][f], b1 = W^T[qb+tig+4][f], f = ft*8+gid
            const unsigned* wq0 = s_wb + (size_t)((k * 4 + ks) * 8 + tig) * WST + gid;
            const unsigned* wq4 = wq0 + 4 * WST;

            #pragma unroll
            for (int ft = 0; ft < 8; ++ft) {
                unsigned b0 = wq0[ft * 8];
                unsigned b1 = wq4[ft * 8];
                MMA_TF32(acc[0][ft], a00, a01, a02, a03, b0, b1);
                MMA_TF32(acc[1][ft], a10, a11, a12, a13, b0, b1);
            }
        }
    }

    // ---- epilogue: D row = n (gid/gid+8), col = f (2*tig, 2*tig+1) ----
    float* obase = out + (size_t)bt * FF * NN + n_base + n0;
    #pragma unroll
    for (int mt = 0; mt < 2; ++mt) {
        #pragma unroll
        for (int ft = 0; ft < 8; ++ft) {
            int f0 = ft * 8 + 2 * tig;
            float* p = obase + mt * 16 + (size_t)f0 * NN;
            p[0]      = acc[mt][ft][0];   // (n,   f0)
            p[NN]     = acc[mt][ft][1];   // (n,   f0+1)
            p[8]      = acc[mt][ft][2];   // (n+8, f0)
            p[NN + 8] = acc[mt][ft][3];   // (n+8, f0+1)
        }
    }
}

extern "C" void kernel_launch(void* const* d_in, const int* in_sizes, int n_in,
                              void* d_out, int out_size)
{
    const float* x      = (const float*)d_in[0];
    const float* coords = (const float*)d_in[1];
    const float* weight = (const float*)d_in[2];
    const void*  sig    = d_in[3];
    float*       out    = (float*)d_out;

    size_t smem_bytes = (size_t)SMEM_FLOATS * sizeof(float);   // ~126 KB
    cudaFuncSetAttribute(swconv1d_mma_kernel,
                         cudaFuncAttributeMaxDynamicSharedMemorySize,
                         (int)smem_bytes);

    dim3 grid(NN / NT, BB * TT);   // (64, 16)
    swconv1d_mma_kernel<<<grid, 256, smem_bytes>>>(x, coords, weight, sig, out);
}